// round 2
// baseline (speedup 1.0000x reference)
#include <cuda_runtime.h>
#include <math.h>

#define NN 100000
#define EE 500000
#define GG 2048
#define DIM 128
#define OUTD 64
#define BN_EPS 1e-5f

// ---------------- scratch (device globals; no allocation allowed) ----------------
__device__ float g_agg[NN * DIM];
__device__ float g_y[NN * DIM];
__device__ float g_h[NN * DIM];
__device__ float g_pool[GG * DIM];
__device__ float g_code[GG * OUTD];
__device__ float g_colsum[DIM];
__device__ float g_colsumsq[DIM];
__device__ float g_scale[DIM];
__device__ float g_shift[DIM];
__device__ int g_src[EE];
__device__ int g_dst[EE];
__device__ int g_batch[NN];

// ---------------- index canonicalization (dtype-robust) ----------------
// Detects whether the raw buffer is int64 or int32 by inspecting the high
// words: values are < NN (fits in 31 bits), so an int64 buffer read as int32
// has zeros at every odd position. Genuine int32 index data has ~0 chance of
// 64 consecutive odd-position zeros. Purely device-side -> graph-safe.
__device__ __forceinline__ bool is_int64_layout(const int* raw, int n_vals) {
    int nchk = n_vals < 64 ? n_vals : 64;
    for (int i = 0; i < nchk; i++)
        if (raw[2 * i + 1] != 0) return false;
    return true;
}

__global__ void convert_edges(const int* __restrict__ raw, int* __restrict__ src,
                              int* __restrict__ dst) {
    bool w = is_int64_layout(raw, 2 * EE);
    int i = blockIdx.x * blockDim.x + threadIdx.x;
    int stride = gridDim.x * blockDim.x;
    if (w) {
        const long long* r = (const long long*)raw;
        for (int e = i; e < EE; e += stride) {
            src[e] = (int)r[e];
            dst[e] = (int)r[EE + e];
        }
    } else {
        for (int e = i; e < EE; e += stride) {
            src[e] = raw[e];
            dst[e] = raw[EE + e];
        }
    }
}

__global__ void convert_batch(const int* __restrict__ raw, int* __restrict__ out) {
    bool w = is_int64_layout(raw, NN);
    int i = blockIdx.x * blockDim.x + threadIdx.x;
    int stride = gridDim.x * blockDim.x;
    if (w) {
        const long long* r = (const long long*)raw;
        for (int n = i; n < NN; n += stride) out[n] = (int)r[n];
    } else {
        for (int n = i; n < NN; n += stride) out[n] = raw[n];
    }
}

// ---------------- utility kernels ----------------
__global__ void zero_f(float* __restrict__ p, int n) {
    int i = blockIdx.x * blockDim.x + threadIdx.x;
    int stride = gridDim.x * blockDim.x;
    float4* p4 = (float4*)p;
    int n4 = n >> 2;
    for (int k = i; k < n4; k += stride) p4[k] = make_float4(0.f, 0.f, 0.f, 0.f);
}

__global__ void zero_stats(float* __restrict__ a, float* __restrict__ b) {
    int i = threadIdx.x;
    if (i < DIM) { a[i] = 0.f; b[i] = 0.f; }
}

// ---------------- edge aggregation: agg[dst] += h[src]  (32 lanes/edge) ----------------
__global__ void edge_agg(const float* __restrict__ h, const int* __restrict__ src,
                         const int* __restrict__ dst, float* __restrict__ agg, int E) {
    int t = blockIdx.x * blockDim.x + threadIdx.x;
    int e = t >> 5;
    int lane = t & 31;
    if (e >= E) return;
    int s = src[e];
    int d = dst[e];
    if ((unsigned)s >= NN || (unsigned)d >= NN) return;  // defensive, never taken
    float4 v = ((const float4*)(h + (size_t)s * DIM))[lane];
    float* a = agg + (size_t)d * DIM + lane * 4;
    atomicAdd(a + 0, v.x);
    atomicAdd(a + 1, v.y);
    atomicAdd(a + 2, v.z);
    atomicAdd(a + 3, v.w);
}

// ---------------- pooling: pool[batch[n]] += h[n] ----------------
__global__ void pool_kernel(const float* __restrict__ h, const int* __restrict__ batch,
                            float* __restrict__ pool, int n_nodes) {
    int t = blockIdx.x * blockDim.x + threadIdx.x;
    int n = t >> 5;
    int lane = t & 31;
    if (n >= n_nodes) return;
    int g = batch[n];
    if ((unsigned)g >= GG) return;  // defensive, never taken
    float4 v = ((const float4*)(h + (size_t)n * DIM))[lane];
    float* p = pool + (size_t)g * DIM + lane * 4;
    atomicAdd(p + 0, v.x);
    atomicAdd(p + 1, v.y);
    atomicAdd(p + 2, v.z);
    atomicAdd(p + 3, v.w);
}

// ---------------- BN column statistics ----------------
__global__ void bn_stats(const float* __restrict__ y, float* __restrict__ colsum,
                         float* __restrict__ colsumsq, int M) {
    __shared__ float s1[256], s2[256];
    int col = threadIdx.x & 127;
    int sub = threadIdx.x >> 7;  // 0 or 1
    int r0 = blockIdx.x * 256;
    int rend = min(r0 + 256, M);
    float s = 0.f, sq = 0.f;
    for (int r = r0 + sub; r < rend; r += 2) {
        float v = y[(size_t)r * DIM + col];
        s += v;
        sq += v * v;
    }
    s1[threadIdx.x] = s;
    s2[threadIdx.x] = sq;
    __syncthreads();
    if (sub == 0) {
        atomicAdd(&colsum[col], s1[col] + s1[col + 128]);
        atomicAdd(&colsumsq[col], s2[col] + s2[col + 128]);
    }
}

__global__ void bn_finalize(const float* __restrict__ colsum, const float* __restrict__ colsumsq,
                            const float* __restrict__ gamma, const float* __restrict__ beta,
                            float* __restrict__ scale, float* __restrict__ shift, int M) {
    int c = threadIdx.x;
    if (c >= DIM) return;
    float invM = 1.f / (float)M;
    float mean = colsum[c] * invM;
    float var = colsumsq[c] * invM - mean * mean;
    float sc = gamma[c] * rsqrtf(var + BN_EPS);
    scale[c] = sc;
    shift[c] = beta[c] - mean * sc;
}

// ---------------- GEMM: C[M,128] = act(A'[M,128] @ W[128,128] + b) ----------------
// IN_MODE 1: A' = A0 + A1 ; 2: A' = relu(scale*A0 + shift)
// 256 threads, 64-row tile, each thread computes 8 rows x 4 cols.
#define GEMM_SMEM ((128 * 128 + 64 * 128) * 4)
template <int IN_MODE, bool OUT_RELU>
__global__ __launch_bounds__(256, 2) void gemm128(
    const float* __restrict__ A0, const float* __restrict__ A1,
    const float* __restrict__ scale, const float* __restrict__ shift,
    const float* __restrict__ W, const float* __restrict__ bias,
    float* __restrict__ C, int M) {
    extern __shared__ float sm[];
    float* Wsm = sm;             // 128*128
    float* Asm = sm + 128 * 128; // 64*128
    int tid = threadIdx.x;
    int row0 = blockIdx.x * 64;

    // stage W (16384 floats, float4)
    {
        const float4* Wv = (const float4*)W;
        float4* Wsv = (float4*)Wsm;
#pragma unroll
        for (int i = 0; i < 16; i++) Wsv[tid + i * 256] = Wv[tid + i * 256];
    }
    // stage A tile with input transform (2048 float4)
    {
        float4* Asv = (float4*)Asm;
#pragma unroll
        for (int i = 0; i < 8; i++) {
            int idx = tid + i * 256;
            int r = idx >> 5;
            int c4 = idx & 31;
            int gr = row0 + r;
            float4 v = make_float4(0.f, 0.f, 0.f, 0.f);
            if (gr < M) {
                v = ((const float4*)A0)[(size_t)gr * 32 + c4];
                if (IN_MODE == 1) {
                    float4 u = ((const float4*)A1)[(size_t)gr * 32 + c4];
                    v.x += u.x; v.y += u.y; v.z += u.z; v.w += u.w;
                } else if (IN_MODE == 2) {
                    float4 sc = ((const float4*)scale)[c4];
                    float4 sh = ((const float4*)shift)[c4];
                    v.x = fmaxf(v.x * sc.x + sh.x, 0.f);
                    v.y = fmaxf(v.y * sc.y + sh.y, 0.f);
                    v.z = fmaxf(v.z * sc.z + sh.z, 0.f);
                    v.w = fmaxf(v.w * sc.w + sh.w, 0.f);
                }
            }
            Asv[idx] = v;
        }
    }
    __syncthreads();

    int cid = tid & 31;  // column group: cols cid*4..+3
    int rid = tid >> 5;  // row group: rows rid*8..+7
    float acc[8][4];
#pragma unroll
    for (int i = 0; i < 8; i++)
#pragma unroll
        for (int j = 0; j < 4; j++) acc[i][j] = 0.f;

    const float4* Asv = (const float4*)Asm;
    const float4* Wsv = (const float4*)Wsm;
#pragma unroll
    for (int k4 = 0; k4 < 32; k4++) {
        float4 av[8];
#pragma unroll
        for (int i = 0; i < 8; i++) av[i] = Asv[(rid * 8 + i) * 32 + k4];
#pragma unroll
        for (int kk = 0; kk < 4; kk++) {
            float4 wv = Wsv[(k4 * 4 + kk) * 32 + cid];
#pragma unroll
            for (int i = 0; i < 8; i++) {
                float a = (kk == 0) ? av[i].x : (kk == 1) ? av[i].y : (kk == 2) ? av[i].z : av[i].w;
                acc[i][0] += a * wv.x;
                acc[i][1] += a * wv.y;
                acc[i][2] += a * wv.z;
                acc[i][3] += a * wv.w;
            }
        }
    }

    float4 bv = ((const float4*)bias)[cid];
#pragma unroll
    for (int i = 0; i < 8; i++) {
        int gr = row0 + rid * 8 + i;
        if (gr < M) {
            float4 o;
            o.x = acc[i][0] + bv.x;
            o.y = acc[i][1] + bv.y;
            o.z = acc[i][2] + bv.z;
            o.w = acc[i][3] + bv.w;
            if (OUT_RELU) {
                o.x = fmaxf(o.x, 0.f); o.y = fmaxf(o.y, 0.f);
                o.z = fmaxf(o.z, 0.f); o.w = fmaxf(o.w, 0.f);
            }
            ((float4*)C)[(size_t)gr * 32 + cid] = o;
        }
    }
}

// ---------------- code MLP branch (per-graph block) ----------------
__global__ void code_mlp(const float* __restrict__ code_x,
                         const float* __restrict__ w1, const float* __restrict__ b1,
                         const float* __restrict__ w2, const float* __restrict__ b2,
                         const float* __restrict__ w3, const float* __restrict__ b3,
                         float* __restrict__ code_out) {
    __shared__ float buf0[128], buf1[128];
    __shared__ float red[64];
    __shared__ float s_mx, s_lse;
    int g = blockIdx.x, j = threadIdx.x;
    buf0[j] = code_x[(size_t)g * 128 + j];
    __syncthreads();
    float acc = b1[j];
    for (int k = 0; k < 128; k++) acc += buf0[k] * w1[k * 128 + j];
    buf1[j] = fmaxf(acc, 0.f);
    __syncthreads();
    float acc2 = b2[j];
    for (int k = 0; k < 128; k++) acc2 += buf1[k] * w2[k * 128 + j];
    buf0[j] = fmaxf(acc2, 0.f);
    __syncthreads();
    float v = 0.f;
    if (j < 64) {
        v = b3[j];
        for (int k = 0; k < 128; k++) v += buf0[k] * w3[k * 64 + j];
        red[j] = v;
    }
    __syncthreads();
    if (j == 0) {
        float m = red[0];
        for (int i = 1; i < 64; i++) m = fmaxf(m, red[i]);
        float s = 0.f;
        for (int i = 0; i < 64; i++) s += expf(red[i] - m);
        s_mx = m;
        s_lse = logf(s);
    }
    __syncthreads();
    if (j < 64) code_out[(size_t)g * 64 + j] = v - s_mx - s_lse;
}

// ---------------- head: pooled MLP + concat + final log_softmax ----------------
__global__ void head_kernel(const float* __restrict__ pool,
                            const float* __restrict__ l1w, const float* __restrict__ l1b,
                            const float* __restrict__ l2w, const float* __restrict__ l2b,
                            const float* __restrict__ code,
                            const float* __restrict__ finw, const float* __restrict__ finb,
                            float* __restrict__ out) {
    __shared__ float p[128], t[128], cc[128];
    __shared__ float r0[128], r1[128];
    int g = blockIdx.x, j = threadIdx.x;
    p[j] = pool[(size_t)g * 128 + j];
    __syncthreads();
    float a = l1b[j];
    for (int k = 0; k < 128; k++) a += p[k] * l1w[k * 128 + j];
    t[j] = fmaxf(a, 0.f);
    __syncthreads();
    if (j < 64) {
        float v = l2b[j];
        for (int k = 0; k < 128; k++) v += t[k] * l2w[k * 64 + j];
        cc[64 + j] = v;                      // trans_emb
        cc[j] = code[(size_t)g * 64 + j];    // code_emb
    }
    __syncthreads();
    r0[j] = cc[j] * finw[j * 2 + 0];
    r1[j] = cc[j] * finw[j * 2 + 1];
    __syncthreads();
    if (j == 0) {
        float o0 = finb[0], o1 = finb[1];
        for (int k = 0; k < 128; k++) { o0 += r0[k]; o1 += r1[k]; }
        float m = fmaxf(o0, o1);
        float l = m + logf(expf(o0 - m) + expf(o1 - m));
        out[(size_t)g * 2 + 0] = o0 - l;
        out[(size_t)g * 2 + 1] = o1 - l;
    }
}

// ---------------- launcher ----------------
extern "C" void kernel_launch(void* const* d_in, const int* in_sizes, int n_in,
                              void* d_out, int out_size) {
    const float* x = (const float*)d_in[0];
    const int* ei_raw = (const int*)d_in[1];
    const int* batch_raw = (const int*)d_in[2];
    const float* code_x = (const float*)d_in[3];
    const float* c1_w1 = (const float*)d_in[4];
    const float* c1_b1 = (const float*)d_in[5];
    const float* c1_g = (const float*)d_in[6];
    const float* c1_be = (const float*)d_in[7];
    const float* c1_w2 = (const float*)d_in[8];
    const float* c1_b2 = (const float*)d_in[9];
    const float* c2_w1 = (const float*)d_in[10];
    const float* c2_b1 = (const float*)d_in[11];
    const float* c2_g = (const float*)d_in[12];
    const float* c2_be = (const float*)d_in[13];
    const float* c2_w2 = (const float*)d_in[14];
    const float* c2_b2 = (const float*)d_in[15];
    const float* gl1_w = (const float*)d_in[16];
    const float* gl1_b = (const float*)d_in[17];
    const float* gl2_w = (const float*)d_in[18];
    const float* gl2_b = (const float*)d_in[19];
    const float* fc1_w = (const float*)d_in[20];
    const float* fc1_b = (const float*)d_in[21];
    const float* fc2_w = (const float*)d_in[22];
    const float* fc2_b = (const float*)d_in[23];
    const float* fc3_w = (const float*)d_in[24];
    const float* fc3_b = (const float*)d_in[25];
    const float* fin_w = (const float*)d_in[26];
    const float* fin_b = (const float*)d_in[27];
    float* out = (float*)d_out;

    float *agg, *y, *h, *pool, *code, *colsum, *colsumsq, *scale, *shift;
    int *srcp, *dstp, *batchp;
    cudaGetSymbolAddress((void**)&agg, g_agg);
    cudaGetSymbolAddress((void**)&y, g_y);
    cudaGetSymbolAddress((void**)&h, g_h);
    cudaGetSymbolAddress((void**)&pool, g_pool);
    cudaGetSymbolAddress((void**)&code, g_code);
    cudaGetSymbolAddress((void**)&colsum, g_colsum);
    cudaGetSymbolAddress((void**)&colsumsq, g_colsumsq);
    cudaGetSymbolAddress((void**)&scale, g_scale);
    cudaGetSymbolAddress((void**)&shift, g_shift);
    cudaGetSymbolAddress((void**)&srcp, g_src);
    cudaGetSymbolAddress((void**)&dstp, g_dst);
    cudaGetSymbolAddress((void**)&batchp, g_batch);

    cudaFuncSetAttribute(gemm128<1, false>, cudaFuncAttributeMaxDynamicSharedMemorySize, GEMM_SMEM);
    cudaFuncSetAttribute(gemm128<2, true>, cudaFuncAttributeMaxDynamicSharedMemorySize, GEMM_SMEM);

    const int gemm_blocks = (NN + 63) / 64;           // 1563
    const int stat_blocks = (NN + 255) / 256;         // 391
    const int edge_blocks = (EE * 32 + 255) / 256;    // 62500
    const int pool_blocks = (NN * 32 + 255) / 256;    // 12500

    // canonicalize index dtypes first
    convert_edges<<<512, 256>>>(ei_raw, srcp, dstp);
    convert_batch<<<256, 256>>>(batch_raw, batchp);

    // independent branch (fills pipeline)
    code_mlp<<<GG, 128>>>(code_x, fc1_w, fc1_b, fc2_w, fc2_b, fc3_w, fc3_b, code);

    zero_f<<<4096, 256>>>(agg, NN * DIM);
    zero_f<<<64, 256>>>(pool, GG * DIM);

    // ---- conv1 ----
    edge_agg<<<edge_blocks, 256>>>(x, srcp, dstp, agg, EE);
    gemm128<1, false><<<gemm_blocks, 256, GEMM_SMEM>>>(x, agg, nullptr, nullptr, c1_w1, c1_b1, y, NN);
    zero_stats<<<1, 128>>>(colsum, colsumsq);
    bn_stats<<<stat_blocks, 256>>>(y, colsum, colsumsq, NN);
    bn_finalize<<<1, 128>>>(colsum, colsumsq, c1_g, c1_be, scale, shift, NN);
    gemm128<2, true><<<gemm_blocks, 256, GEMM_SMEM>>>(y, nullptr, scale, shift, c1_w2, c1_b2, h, NN);

    // ---- conv2 ----
    zero_f<<<4096, 256>>>(agg, NN * DIM);
    edge_agg<<<edge_blocks, 256>>>(h, srcp, dstp, agg, EE);
    gemm128<1, false><<<gemm_blocks, 256, GEMM_SMEM>>>(h, agg, nullptr, nullptr, c2_w1, c2_b1, y, NN);
    zero_stats<<<1, 128>>>(colsum, colsumsq);
    bn_stats<<<stat_blocks, 256>>>(y, colsum, colsumsq, NN);
    bn_finalize<<<1, 128>>>(colsum, colsumsq, c2_g, c2_be, scale, shift, NN);
    gemm128<2, true><<<gemm_blocks, 256, GEMM_SMEM>>>(y, nullptr, scale, shift, c2_w2, c2_b2, h, NN);

    // ---- pool + heads ----
    pool_kernel<<<pool_blocks, 256>>>(h, batchp, pool, NN);
    head_kernel<<<GG, 128>>>(pool, gl1_w, gl1_b, gl2_w, gl2_b, code, fin_w, fin_b, out);
}